// round 1
// baseline (speedup 1.0000x reference)
#include <cuda_runtime.h>
#include <math.h>

// Problem constants (from reference: B=16, L=256)
#define LQ 256
#define BQ 16
#define CHART (BQ * LQ * LQ)
#define NBLK_LOSS 1024

// Scratch charts as __device__ globals (no allocation allowed).
// g_S  : inside chart s[b,i,j]            (row-major)
// g_ST : transposed inside chart sT[b,j,i] = s[b,i,j]
// g_BL : outside credit received as LEFT child,  indexed [b,i,k]
// g_BT : outside credit received as RIGHT child, transposed: [b,j,k+1]
// marginal(i,j) = g_BL[b,i,j] + g_BT[b,j,i] (+1 at root (0,len-1))
__device__ float g_S[CHART];
__device__ float g_ST[CHART];
__device__ float g_BL[CHART];
__device__ float g_BT[CHART];
__device__ int   g_lens[BQ];
__device__ double g_part[NBLK_LOSS * 3];

__device__ __forceinline__ float warp_max(float v) {
#pragma unroll
    for (int o = 16; o; o >>= 1) v = fmaxf(v, __shfl_xor_sync(0xffffffffu, v, o));
    return v;
}
__device__ __forceinline__ float warp_sum(float v) {
#pragma unroll
    for (int o = 16; o; o >>= 1) v += __shfl_xor_sync(0xffffffffu, v, o);
    return v;
}

// ---------------------------------------------------------------------------
// Zero the outside accumulators.
__global__ void k_zero() {
    int idx = blockIdx.x * blockDim.x + threadIdx.x;
    int stride = gridDim.x * blockDim.x;
    for (int i = idx; i < CHART; i += stride) { g_BL[i] = 0.f; g_BT[i] = 0.f; }
}

// ---------------------------------------------------------------------------
// Init: diag of inside chart = lg diag; compute lens[b] from maskspan row 0.
// Dtype hedge: bool stored as 1 byte (expected) gives a row sum in [128,256];
// if it were int32, the byte-sum of the first 256 bytes is <= 64, and we
// re-read as int32 (buffer is large enough in that case).
__global__ void k_init(const float* __restrict__ lg,
                       const unsigned char* __restrict__ mspanB,
                       const int* __restrict__ mspanI) {
    int b = blockIdx.x, t = threadIdx.x;  // 256 threads
    float d = lg[((b * LQ) + t) * LQ + t];
    g_S[((b * LQ) + t) * LQ + t] = d;
    g_ST[((b * LQ) + t) * LQ + t] = d;

    __shared__ int sh[256];
    sh[t] = (int)mspanB[b * LQ * LQ + t];
    __syncthreads();
    for (int o = 128; o; o >>= 1) { if (t < o) sh[t] += sh[t + o]; __syncthreads(); }
    int bs = sh[0];
    __syncthreads();
    int len;
    if (bs >= 128) {
        len = bs;  // bool-as-byte layout
    } else {
        sh[t] = mspanI[b * LQ * LQ + t];  // int32 layout
        __syncthreads();
        for (int o = 128; o; o >>= 1) { if (t < o) sh[t] += sh[t + o]; __syncthreads(); }
        len = sh[0];
    }
    if (t == 0) g_lens[b] = len;
}

// ---------------------------------------------------------------------------
// Inside step for width w: s[i,i+w] = lg[i,i+w] + logsumexp_k(s[i,i+k] + s[i+k+1,i+w])
// One warp per cell; 8 warps per block. Both operand streams contiguous.
__global__ void k_inside(const float* __restrict__ lg, int w) {
    int b = blockIdx.y;
    int lane = threadIdx.x & 31;
    int i = blockIdx.x * 8 + (threadIdx.x >> 5);
    int j = i + w;
    if (j >= g_lens[b]) return;

    const float* __restrict__ Lrow = g_S  + ((b * LQ) + i) * LQ + i;       // s[i, i+t]
    const float* __restrict__ Rrow = g_ST + ((b * LQ) + j) * LQ + (i + 1); // s[i+1+t, j]

    const float NI = __int_as_float(0xff800000);  // -inf
    float vals[8];
    float vmax = NI;
#pragma unroll
    for (int c = 0; c < 8; c++) {
        int t = lane + c * 32;
        float v = NI;
        if (t < w) v = Lrow[t] + Rrow[t];
        vals[c] = v;
        vmax = fmaxf(vmax, v);
    }
    vmax = warp_max(vmax);
    float s = 0.f;
#pragma unroll
    for (int c = 0; c < 8; c++) {
        int t = lane + c * 32;
        if (t < w) s += __expf(vals[c] - vmax);
    }
    s = warp_sum(s);
    if (lane == 0) {
        float nv = vmax + __logf(s) + lg[((b * LQ) + i) * LQ + j];
        g_S [((b * LQ) + i) * LQ + j] = nv;
        g_ST[((b * LQ) + j) * LQ + i] = nv;
    }
}

// ---------------------------------------------------------------------------
// Outside step for width w (descending). Parent (i, j=i+w) with finalized
// credit mu distributes mu * softmax_weight(k) to children (i,k) and (k+1,j).
// Left-child credits go into row i of g_BL; right-child credits into row j of
// g_BT (transposed). Each such row is written by exactly one parent per step,
// so plain read-modify-write is race-free and deterministic.
__global__ void k_outside(const float* __restrict__ lg, int w) {
    int b = blockIdx.y;
    int lane = threadIdx.x & 31;
    int i = blockIdx.x * 8 + (threadIdx.x >> 5);
    int j = i + w;
    int len = g_lens[b];
    if (j >= len) return;

    int pidx = ((b * LQ) + i) * LQ + j;
    float mu = g_BL[pidx] + g_BT[((b * LQ) + j) * LQ + i];
    if (i == 0 && j == len - 1) mu += 1.f;  // root seed: d logZ / d s[0,len-1] = 1
    if (mu == 0.f) return;

    float cadd = lg[pidx] - g_S[pidx];
    const float* __restrict__ Lrow = g_S  + ((b * LQ) + i) * LQ + i;
    const float* __restrict__ Rrow = g_ST + ((b * LQ) + j) * LQ + (i + 1);
    float* BLrow = g_BL + ((b * LQ) + i) * LQ + i;        // child (i, i+t)
    float* BTrow = g_BT + ((b * LQ) + j) * LQ + (i + 1);  // child (i+1+t, j)

#pragma unroll
    for (int c = 0; c < 8; c++) {
        int t = lane + c * 32;
        if (t < w) {
            float e = mu * __expf(Lrow[t] + Rrow[t] + cadd);  // exponent <= 0 by construction
            BLrow[t] += e;
            BTrow[t] += e;
        }
    }
}

// ---------------------------------------------------------------------------
// Fused loss reduction. Masks reconstructed analytically from lens.
__global__ void k_loss(const float* __restrict__ ph, const float* __restrict__ pt,
                       const float* __restrict__ ph_arc,
                       const int* __restrict__ spans_ind,
                       const int* __restrict__ ph_ind,
                       const int* __restrict__ pt_ind) {
    double a_sp = 0.0, a_ph = 0.0, a_pt = 0.0;
    int stride = gridDim.x * blockDim.x;
    for (int idx = blockIdx.x * blockDim.x + threadIdx.x; idx < CHART; idx += stride) {
        int b = idx >> 16;
        int i = (idx >> 8) & 255;
        int j = idx & 255;
        int len = g_lens[b];
        if (i < len && j < len) {
            // BCE(ph), BCE(pt) over maskarc (stable softplus, matches jax.nn.softplus)
            float x = ph[idx];
            float y = (float)ph_ind[idx];
            a_ph += (double)(fmaxf(x, 0.f) + log1pf(expf(-fabsf(x))) - x * y);
            x = pt[idx]; y = (float)pt_ind[idx];
            a_pt += (double)(fmaxf(x, 0.f) + log1pf(expf(-fabsf(x))) - x * y);
            if (i <= j) {  // maskspan
                float marg = g_BL[idx] + g_BT[((b * LQ) + j) * LQ + i];
                if (i == 0 && j == len - 1) marg += 1.f;
                float xa = ph_arc[idx];
                float p = 1.f / (1.f + expf(-xa));
                float pm = p * marg;
                a_sp += (double)((spans_ind[idx] >= 2) ? logf(pm) : logf(1.f - pm));
            }
        }
    }
    __shared__ double s0[256], s1[256], s2[256];
    int t = threadIdx.x;
    s0[t] = a_sp; s1[t] = a_ph; s2[t] = a_pt;
    __syncthreads();
    for (int o = 128; o; o >>= 1) {
        if (t < o) { s0[t] += s0[t + o]; s1[t] += s1[t + o]; s2[t] += s2[t + o]; }
        __syncthreads();
    }
    if (t == 0) {
        g_part[blockIdx.x * 3 + 0] = s0[0];
        g_part[blockIdx.x * 3 + 1] = s1[0];
        g_part[blockIdx.x * 3 + 2] = s2[0];
    }
}

__global__ void k_final(float* __restrict__ out) {
    int t = threadIdx.x;
    double a0 = 0, a1 = 0, a2 = 0;
    for (int p = t; p < NBLK_LOSS; p += 256) {
        a0 += g_part[p * 3 + 0];
        a1 += g_part[p * 3 + 1];
        a2 += g_part[p * 3 + 2];
    }
    __shared__ double s0[256], s1[256], s2[256];
    s0[t] = a0; s1[t] = a1; s2[t] = a2;
    __syncthreads();
    for (int o = 128; o; o >>= 1) {
        if (t < o) { s0[t] += s0[t + o]; s1[t] += s1[t + o]; s2[t] += s2[t + o]; }
        __syncthreads();
    }
    if (t == 0) {
        double lens_sum = 0, arc = 0;
        for (int b = 0; b < BQ; b++) {
            double l = (double)g_lens[b];
            lens_sum += l;
            arc += l * l;  // maskarc.sum() = sum len^2
        }
        double loss_spans = -s0[0] / lens_sum;
        double loss_ph = s1[0] / arc;
        double loss_pt = s2[0] / arc;
        out[0] = (float)(0.1 * loss_spans + 0.9 * (loss_ph + loss_pt));
    }
}

// ---------------------------------------------------------------------------
extern "C" void kernel_launch(void* const* d_in, const int* in_sizes, int n_in,
                              void* d_out, int out_size) {
    const float* span_logits = (const float*)d_in[0];
    const float* ph          = (const float*)d_in[1];
    const float* pt          = (const float*)d_in[2];
    const float* ph_arc      = (const float*)d_in[3];
    const int*   spans_ind   = (const int*)d_in[4];
    const int*   ph_ind      = (const int*)d_in[5];
    const int*   pt_ind      = (const int*)d_in[6];
    // d_in[7] = maskarc (unused; reconstructed from lens)
    const void*  maskspan    = d_in[8];

    k_zero<<<512, 256>>>();
    k_init<<<BQ, 256>>>(span_logits,
                        (const unsigned char*)maskspan,
                        (const int*)maskspan);

    for (int w = 1; w < LQ; w++) {
        dim3 grid((LQ - w + 7) / 8, BQ);
        k_inside<<<grid, 256>>>(span_logits, w);
    }
    for (int w = LQ - 1; w >= 1; w--) {
        dim3 grid((LQ - w + 7) / 8, BQ);
        k_outside<<<grid, 256>>>(span_logits, w);
    }

    k_loss<<<NBLK_LOSS, 256>>>(ph, pt, ph_arc, spans_ind, ph_ind, pt_ind);
    k_final<<<1, 256>>>((float*)d_out);
}